// round 4
// baseline (speedup 1.0000x reference)
#include <cuda_runtime.h>
#include <cuda_bf16.h>
#include <cstddef>

#define IDIM 256
#define JDIM 256
#define CDIM 256
#define HDIM 8
#define DDIM 64
#define HD   512    // H*D
#define NROW 65536  // I*J

// ---------------- device-global scratch (no allocations allowed) ----------------
__device__ float g_xn[(size_t)NROW * CDIM];   // 64 MB  layernormed x
__device__ float g_q [(size_t)NROW * HD];     // 128 MB
__device__ float g_k [(size_t)NROW * HD];
__device__ float g_v [(size_t)NROW * HD];
__device__ float g_g [(size_t)NROW * HD];     // raw gate projection (pre-sigmoid)
__device__ float g_o [(size_t)NROW * HD];     // gated attention output

// ============================= LayerNorm ==============================
// one block per (i,j) row, 256 threads = 256 channels
__global__ void ln_kernel(const float* __restrict__ x,
                          const float* __restrict__ gamma,
                          const float* __restrict__ beta) {
    int row = blockIdx.x;
    int tid = threadIdx.x;
    float v = x[(size_t)row * CDIM + tid];

    __shared__ float red[8];
    float s = v;
    #pragma unroll
    for (int o = 16; o > 0; o >>= 1) s += __shfl_xor_sync(0xffffffffu, s, o);
    if ((tid & 31) == 0) red[tid >> 5] = s;
    __syncthreads();
    float tot = 0.f;
    #pragma unroll
    for (int w = 0; w < 8; w++) tot += red[w];
    float mean = tot * (1.0f / CDIM);
    float d = v - mean;
    __syncthreads();

    float s2 = d * d;
    #pragma unroll
    for (int o = 16; o > 0; o >>= 1) s2 += __shfl_xor_sync(0xffffffffu, s2, o);
    if ((tid & 31) == 0) red[tid >> 5] = s2;
    __syncthreads();
    float var = 0.f;
    #pragma unroll
    for (int w = 0; w < 8; w++) var += red[w];
    var *= (1.0f / CDIM);
    float rstd = rsqrtf(var + 1e-5f);
    g_xn[(size_t)row * CDIM + tid] = d * rstd * gamma[tid] + beta[tid];
}

// ============================= SGEMM 128x128x8 ==============================
// C[M,ldc] = A[M,K] * B[K,ldb]  (+bias).  256 threads, 8x8 per thread.
// mode 0..3: A = g_xn, C = {g_q,g_k,g_v,g_g};  mode 4: A = g_o, C = Cext.
__global__ void __launch_bounds__(256) gemm128(
    const float* __restrict__ Bw, const float* __restrict__ bias,
    float* __restrict__ Cext, int mode, int K, int ldb, int ldc) {

    const float* A;
    float* C;
    if (mode == 4) { A = g_o; C = Cext; }
    else {
        A = g_xn;
        C = (mode == 0) ? g_q : (mode == 1) ? g_k : (mode == 2) ? g_v : g_g;
    }

    __shared__ float As[8][128];
    __shared__ float Bs[8][128];

    const int tid  = threadIdx.x;
    const int m0   = blockIdx.y * 128;
    const int n0   = blockIdx.x * 128;
    const int tx   = (tid & 15) * 8;
    const int ty   = (tid >> 4) * 8;
    const int arow = tid >> 1;
    const int ac   = (tid & 1) * 4;
    const int brow = tid >> 5;
    const int bc   = (tid & 31) * 4;

    float acc[8][8];
    #pragma unroll
    for (int i = 0; i < 8; i++)
        #pragma unroll
        for (int j = 0; j < 8; j++) acc[i][j] = 0.f;

    const float* Aptr = A  + (size_t)(m0 + arow) * K + ac;
    const float* Bptr = Bw + (size_t)brow * ldb + n0 + bc;

    for (int kk = 0; kk < K; kk += 8) {
        float4 av = *(const float4*)(Aptr + kk);
        float4 bv = *(const float4*)(Bptr + (size_t)kk * ldb);
        As[ac + 0][arow] = av.x;
        As[ac + 1][arow] = av.y;
        As[ac + 2][arow] = av.z;
        As[ac + 3][arow] = av.w;
        *(float4*)&Bs[brow][bc] = bv;
        __syncthreads();

        #pragma unroll
        for (int k = 0; k < 8; k++) {
            float a[8], b[8];
            *(float4*)(a)     = *(const float4*)&As[k][ty];
            *(float4*)(a + 4) = *(const float4*)&As[k][ty + 4];
            *(float4*)(b)     = *(const float4*)&Bs[k][tx];
            *(float4*)(b + 4) = *(const float4*)&Bs[k][tx + 4];
            #pragma unroll
            for (int i = 0; i < 8; i++)
                #pragma unroll
                for (int j = 0; j < 8; j++)
                    acc[i][j] = fmaf(a[i], b[j], acc[i][j]);
        }
        __syncthreads();
    }

    #pragma unroll
    for (int i = 0; i < 8; i++) {
        size_t crow = (size_t)(m0 + ty + i) * ldc + n0 + tx;
        #pragma unroll
        for (int j = 0; j < 8; j += 4) {
            float4 o;
            o.x = acc[i][j + 0]; o.y = acc[i][j + 1];
            o.z = acc[i][j + 2]; o.w = acc[i][j + 3];
            if (bias) {
                o.x += bias[n0 + tx + j + 0];
                o.y += bias[n0 + tx + j + 1];
                o.z += bias[n0 + tx + j + 2];
                o.w += bias[n0 + tx + j + 3];
            }
            *(float4*)&C[crow + j] = o;
        }
    }
}

// ============================= Flash attention + gate ==============================
// grid (H, I), 256 threads (one per query j). K,V tiles in dynamic smem (128 KB).
__global__ void __launch_bounds__(256) attn_kernel(const float* __restrict__ mask,
                                                   const float* __restrict__ bg) {
    extern __shared__ float sh[];
    float* Ks = sh;                 // [256][64]
    float* Vs = sh + 256 * 64;      // [256][64]
    __shared__ float bias_s[256];

    const int h   = blockIdx.x;
    const int i   = blockIdx.y;
    const int tid = threadIdx.x;
    const size_t base = ((size_t)i * 256) * HD + h * 64;

    // cooperative load of K, V tiles (float4, coalesced in 256B segments)
    for (int idx = tid; idx < 256 * 16; idx += 256) {
        int r  = idx >> 4;
        int c4 = (idx & 15) * 4;
        *(float4*)&Ks[r * 64 + c4] = *(const float4*)&g_k[base + (size_t)r * HD + c4];
        *(float4*)&Vs[r * 64 + c4] = *(const float4*)&g_v[base + (size_t)r * HD + c4];
    }
    bias_s[tid] = 1e9f * (mask[i * 256 + tid] - 1.0f);
    __syncthreads();

    // q row into registers, pre-scaled by 1/sqrt(D)
    float qr[64];
    #pragma unroll
    for (int c4 = 0; c4 < 64; c4 += 4) {
        float4 t = *(const float4*)&g_q[base + (size_t)tid * HD + c4];
        qr[c4 + 0] = t.x * 0.125f;
        qr[c4 + 1] = t.y * 0.125f;
        qr[c4 + 2] = t.z * 0.125f;
        qr[c4 + 3] = t.w * 0.125f;
    }

    float m = -1e30f, l = 0.f;
    float o[64];
    #pragma unroll
    for (int d = 0; d < 64; d++) o[d] = 0.f;

    // online softmax in chunks of 8 keys (amortizes rescale)
    for (int kk = 0; kk < 256; kk += 8) {
        float s[8];
        #pragma unroll
        for (int c = 0; c < 8; c++) {
            const float* kr = &Ks[(kk + c) * 64];
            float a0 = 0.f, a1 = 0.f, a2 = 0.f, a3 = 0.f;
            #pragma unroll
            for (int d = 0; d < 64; d += 4) {
                a0 = fmaf(qr[d + 0], kr[d + 0], a0);
                a1 = fmaf(qr[d + 1], kr[d + 1], a1);
                a2 = fmaf(qr[d + 2], kr[d + 2], a2);
                a3 = fmaf(qr[d + 3], kr[d + 3], a3);
            }
            s[c] = (a0 + a1) + (a2 + a3) + bias_s[kk + c];
        }
        float cm = s[0];
        #pragma unroll
        for (int c = 1; c < 8; c++) cm = fmaxf(cm, s[c]);
        float mn = fmaxf(m, cm);
        float alpha = __expf(m - mn);
        float p[8];
        float ps = 0.f;
        #pragma unroll
        for (int c = 0; c < 8; c++) { p[c] = __expf(s[c] - mn); ps += p[c]; }
        l = l * alpha + ps;
        #pragma unroll
        for (int d = 0; d < 64; d++) {
            float accv = o[d] * alpha;
            #pragma unroll
            for (int c = 0; c < 8; c++)
                accv = fmaf(p[c], Vs[(kk + c) * 64 + d], accv);
            o[d] = accv;
        }
        m = mn;
    }

    const float inv_l = 1.0f / l;
    // gate: sigmoid(g_proj + bg), then write gated output
    #pragma unroll
    for (int d = 0; d < 64; d++) {
        float gv  = g_g[base + (size_t)tid * HD + d] + bg[h * 64 + d];
        float sig = 1.0f / (1.0f + __expf(-gv));
        g_o[base + (size_t)tid * HD + d] = o[d] * inv_l * sig;
    }
}

// ============================= launch ==============================
extern "C" void kernel_launch(void* const* d_in, const int* in_sizes, int n_in,
                              void* d_out, int out_size) {
    const float* x     = (const float*)d_in[0];
    const float* mask  = (const float*)d_in[1];
    const float* gamma = (const float*)d_in[2];
    const float* beta  = (const float*)d_in[3];
    const float* Wq    = (const float*)d_in[4];
    const float* Wk    = (const float*)d_in[5];
    const float* Wv    = (const float*)d_in[6];
    const float* Wg    = (const float*)d_in[7];
    const float* bg    = (const float*)d_in[8];
    const float* Wo    = (const float*)d_in[9];
    const float* bo    = (const float*)d_in[10];
    float* out = (float*)d_out;

    const int attn_smem = 2 * 256 * 64 * (int)sizeof(float);  // 128 KB
    cudaFuncSetAttribute(attn_kernel, cudaFuncAttributeMaxDynamicSharedMemorySize, attn_smem);

    // 1) LayerNorm
    ln_kernel<<<NROW, 256>>>(x, gamma, beta);

    // 2) projections: Q, K, V, G = xn @ W*  (M=65536, N=512, K=256)
    dim3 gproj(4, 512);
    gemm128<<<gproj, 256>>>(Wq, nullptr, nullptr, 0, CDIM, HD, HD);
    gemm128<<<gproj, 256>>>(Wk, nullptr, nullptr, 1, CDIM, HD, HD);
    gemm128<<<gproj, 256>>>(Wv, nullptr, nullptr, 2, CDIM, HD, HD);
    gemm128<<<gproj, 256>>>(Wg, nullptr, nullptr, 3, CDIM, HD, HD);

    // 3) attention + gate per (h, i)
    attn_kernel<<<dim3(HDIM, IDIM), 256, attn_smem>>>(mask, bg);

    // 4) output projection: out = o @ Wo + bo  (M=65536, N=256, K=512)
    gemm128<<<dim3(2, 512), 256>>>(Wo, bo, out, 4, HD, CDIM, CDIM);
}

// round 6
// speedup vs baseline: 2.4567x; 2.4567x over previous
#include <cuda_runtime.h>
#include <cuda_bf16.h>
#include <cstddef>

#define IDIM 256
#define JDIM 256
#define CDIM 256
#define HDIM 8
#define DDIM 64
#define HD   512    // H*D
#define NROW 65536  // I*J

// ---------------- device-global scratch (no allocations allowed) ----------------
__device__ float g_xn[(size_t)NROW * CDIM];   // layernormed x
__device__ float g_q [(size_t)NROW * HD];
__device__ float g_k [(size_t)NROW * HD];
__device__ float g_v [(size_t)NROW * HD];
__device__ float g_g [(size_t)NROW * HD];     // raw gate projection (pre-sigmoid)
__device__ float g_o [(size_t)NROW * HD];     // gated attention output

// ---------------- tf32 helpers ----------------
__device__ __forceinline__ unsigned tf32r(float x) {
    unsigned u;
    asm("cvt.rna.tf32.f32 %0, %1;" : "=r"(u) : "f"(x));
    return u;
}
__device__ __forceinline__ float tf32rf(float x) {
    return __uint_as_float(tf32r(x));
}
__device__ __forceinline__ void mma_tf32(float* c, const unsigned* a, const unsigned* b) {
    asm volatile(
        "mma.sync.aligned.m16n8k8.row.col.f32.tf32.tf32.f32 "
        "{%0,%1,%2,%3}, {%4,%5,%6,%7}, {%8,%9}, {%0,%1,%2,%3};"
        : "+f"(c[0]), "+f"(c[1]), "+f"(c[2]), "+f"(c[3])
        : "r"(a[0]), "r"(a[1]), "r"(a[2]), "r"(a[3]), "r"(b[0]), "r"(b[1]));
}

// ============================= LayerNorm ==============================
__global__ void ln_kernel(const float* __restrict__ x,
                          const float* __restrict__ gamma,
                          const float* __restrict__ beta) {
    int row = blockIdx.x;
    int tid = threadIdx.x;
    float v = x[(size_t)row * CDIM + tid];

    __shared__ float red[8];
    float s = v;
    #pragma unroll
    for (int o = 16; o > 0; o >>= 1) s += __shfl_xor_sync(0xffffffffu, s, o);
    if ((tid & 31) == 0) red[tid >> 5] = s;
    __syncthreads();
    float tot = 0.f;
    #pragma unroll
    for (int w = 0; w < 8; w++) tot += red[w];
    float mean = tot * (1.0f / CDIM);
    float d = v - mean;
    __syncthreads();

    float s2 = d * d;
    #pragma unroll
    for (int o = 16; o > 0; o >>= 1) s2 += __shfl_xor_sync(0xffffffffu, s2, o);
    if ((tid & 31) == 0) red[tid >> 5] = s2;
    __syncthreads();
    float var = 0.f;
    #pragma unroll
    for (int w = 0; w < 8; w++) var += red[w];
    var *= (1.0f / CDIM);
    float rstd = rsqrtf(var + 1e-5f);
    g_xn[(size_t)row * CDIM + tid] = d * rstd * gamma[tid] + beta[tid];
}

// ============================= TF32 tensor-core GEMM ==============================
// C[M,ldc] = A[M,K] @ B[K,ldb] (+bias). Block tile 128x128, k-chunk 16.
// 8 warps: 2x4 grid of 64x32 warp tiles. mma.sync m16n8k8 tf32.
// mode 0..3: A = g_xn, C = {g_q,g_k,g_v,g_g};  mode 4: A = g_o, C = Cext.
__global__ void __launch_bounds__(256, 2) gemm_tc(
    const float* __restrict__ Bw, const float* __restrict__ bias,
    float* __restrict__ Cext, int mode, int K, int ldb, int ldc) {

    const float* A;
    float* C;
    if (mode == 4) { A = g_o; C = Cext; }
    else {
        A = g_xn;
        C = (mode == 0) ? g_q : (mode == 1) ? g_k : (mode == 2) ? g_v : g_g;
    }

    __shared__ float As[16][132];   // [k][m] transposed, stride 132 (conflict-free)
    __shared__ float Bs[16][132];   // [k][n]

    const int tid  = threadIdx.x;
    const int warp = tid >> 5;
    const int lane = tid & 31;
    const int lq   = lane & 3;    // thread-in-group
    const int lg   = lane >> 2;   // group id
    const int wm   = warp >> 2;   // 0..1
    const int wn   = warp & 3;    // 0..3
    const int m0   = blockIdx.y * 128;
    const int n0   = blockIdx.x * 128;

    float acc[4][4][4];
    #pragma unroll
    for (int i = 0; i < 4; i++)
        #pragma unroll
        for (int j = 0; j < 4; j++)
            #pragma unroll
            for (int e = 0; e < 4; e++) acc[i][j][e] = 0.f;

    for (int kk = 0; kk < K; kk += 16) {
        // ---- load A tile (transpose into [k][m], tf32-round at store) ----
        #pragma unroll
        for (int i = 0; i < 2; i++) {
            int f = i * 256 + tid;          // 512 float4s total
            int r = f >> 2;                 // m row 0..127
            int c4 = f & 3;                 // which float4 along k
            float4 v = *(const float4*)&A[(size_t)(m0 + r) * K + kk + c4 * 4];
            As[c4 * 4 + 0][r] = tf32rf(v.x);
            As[c4 * 4 + 1][r] = tf32rf(v.y);
            As[c4 * 4 + 2][r] = tf32rf(v.z);
            As[c4 * 4 + 3][r] = tf32rf(v.w);
        }
        // ---- load B tile (row-major [k][n]) ----
        #pragma unroll
        for (int i = 0; i < 2; i++) {
            int f = i * 256 + tid;
            int kr = f >> 5;                // 0..15
            int n4 = f & 31;                // float4 col
            float4 v = *(const float4*)&Bw[(size_t)(kk + kr) * ldb + n0 + n4 * 4];
            float4 o;
            o.x = tf32rf(v.x); o.y = tf32rf(v.y); o.z = tf32rf(v.z); o.w = tf32rf(v.w);
            *(float4*)&Bs[kr][n4 * 4] = o;
        }
        __syncthreads();

        #pragma unroll
        for (int ks = 0; ks < 2; ks++) {
            unsigned a[4][4], b[4][2];
            #pragma unroll
            for (int mf = 0; mf < 4; mf++) {
                int mb = wm * 64 + mf * 16 + lg;
                a[mf][0] = __float_as_uint(As[ks * 8 + lq][mb]);
                a[mf][1] = __float_as_uint(As[ks * 8 + lq][mb + 8]);
                a[mf][2] = __float_as_uint(As[ks * 8 + lq + 4][mb]);
                a[mf][3] = __float_as_uint(As[ks * 8 + lq + 4][mb + 8]);
            }
            #pragma unroll
            for (int nf = 0; nf < 4; nf++) {
                int nb = wn * 32 + nf * 8 + lg;
                b[nf][0] = __float_as_uint(Bs[ks * 8 + lq][nb]);
                b[nf][1] = __float_as_uint(Bs[ks * 8 + lq + 4][nb]);
            }
            #pragma unroll
            for (int mf = 0; mf < 4; mf++)
                #pragma unroll
                for (int nf = 0; nf < 4; nf++)
                    mma_tf32(acc[mf][nf], a[mf], b[nf]);
        }
        __syncthreads();
    }

    // ---- epilogue ----
    #pragma unroll
    for (int mf = 0; mf < 4; mf++) {
        int row = m0 + wm * 64 + mf * 16 + lg;
        #pragma unroll
        for (int nf = 0; nf < 4; nf++) {
            int col = n0 + wn * 32 + nf * 8 + 2 * lq;
            float b0 = bias ? bias[col] : 0.f;
            float b1 = bias ? bias[col + 1] : 0.f;
            float2 v0, v1;
            v0.x = acc[mf][nf][0] + b0; v0.y = acc[mf][nf][1] + b1;
            v1.x = acc[mf][nf][2] + b0; v1.y = acc[mf][nf][3] + b1;
            *(float2*)&C[(size_t)row * ldc + col] = v0;
            *(float2*)&C[(size_t)(row + 8) * ldc + col] = v1;
        }
    }
}

// ============================= TF32 flash attention + gate ==============================
// grid (H, I). 512 threads = 16 warps, each warp owns 16 query rows.
// K,V tiles tf32-rounded in smem (stride 68, conflict-free). P staged per-warp
// through smem to re-fragment C-layout -> A-layout for the PV mma.
#define KVSTR 68
#define ATTN_SMEM_FLOATS (2 * 256 * KVSTR + 16 * 16 * KVSTR + 256)

__global__ void __launch_bounds__(512, 1) attn_tc(const float* __restrict__ mask,
                                                  const float* __restrict__ bg) {
    extern __shared__ float sh[];
    float* Ks     = sh;                        // [256][68]
    float* Vs     = sh + 256 * KVSTR;          // [256][68]
    float* Ps     = sh + 2 * 256 * KVSTR;      // [16 warps][16][68]
    float* bias_s = sh + 2 * 256 * KVSTR + 16 * 16 * KVSTR;  // [256]

    const int h    = blockIdx.x;
    const int i    = blockIdx.y;
    const int tid  = threadIdx.x;
    const int warp = tid >> 5;
    const int lane = tid & 31;
    const int lq   = lane & 3;
    const int lg   = lane >> 2;
    const size_t base = ((size_t)i * 256) * HD + h * 64;

    // ---- load + round K,V tiles ----
    for (int idx = tid; idx < 256 * 16; idx += 512) {
        int r  = idx >> 4;
        int c4 = (idx & 15) * 4;
        float4 kv = *(const float4*)&g_k[base + (size_t)r * HD + c4];
        float4 vv = *(const float4*)&g_v[base + (size_t)r * HD + c4];
        float4 ko, vo;
        ko.x = tf32rf(kv.x); ko.y = tf32rf(kv.y); ko.z = tf32rf(kv.z); ko.w = tf32rf(kv.w);
        vo.x = tf32rf(vv.x); vo.y = tf32rf(vv.y); vo.z = tf32rf(vv.z); vo.w = tf32rf(vv.w);
        *(float4*)&Ks[r * KVSTR + c4] = ko;
        *(float4*)&Vs[r * KVSTR + c4] = vo;
    }
    if (tid < 256) bias_s[tid] = 1e9f * (mask[i * 256 + tid] - 1.0f);
    __syncthreads();

    // ---- Q fragments (persistent, pre-scaled by 1/8, tf32-rounded) ----
    const int row0 = warp * 16 + lg;   // rows row0 and row0+8
    unsigned qa[8][4];
    #pragma unroll
    for (int kf = 0; kf < 8; kf++) {
        int col = kf * 8 + lq;
        qa[kf][0] = tf32r(g_q[base + (size_t)row0 * HD + col] * 0.125f);
        qa[kf][1] = tf32r(g_q[base + (size_t)(row0 + 8) * HD + col] * 0.125f);
        qa[kf][2] = tf32r(g_q[base + (size_t)row0 * HD + col + 4] * 0.125f);
        qa[kf][3] = tf32r(g_q[base + (size_t)(row0 + 8) * HD + col + 4] * 0.125f);
    }

    float oc[8][4];
    #pragma unroll
    for (int nf = 0; nf < 8; nf++)
        #pragma unroll
        for (int e = 0; e < 4; e++) oc[nf][e] = 0.f;

    float m0v = -1e30f, m1v = -1e30f, l0 = 0.f, l1 = 0.f;
    float* Pw = Ps + warp * 16 * KVSTR;

    for (int kc = 0; kc < 256; kc += 64) {
        // ---- S = Q @ K^T chunk [16 x 64] ----
        float sc[8][4];
        #pragma unroll
        for (int nf = 0; nf < 8; nf++) {
            sc[nf][0] = sc[nf][1] = sc[nf][2] = sc[nf][3] = 0.f;
            int key = kc + nf * 8 + lg;
            #pragma unroll
            for (int kb = 0; kb < 8; kb++) {
                unsigned b[2];
                b[0] = __float_as_uint(Ks[key * KVSTR + kb * 8 + lq]);
                b[1] = __float_as_uint(Ks[key * KVSTR + kb * 8 + lq + 4]);
                mma_tf32(sc[nf], qa[kb], b);
            }
            float bb0 = bias_s[kc + nf * 8 + 2 * lq];
            float bb1 = bias_s[kc + nf * 8 + 2 * lq + 1];
            sc[nf][0] += bb0; sc[nf][1] += bb1;
            sc[nf][2] += bb0; sc[nf][3] += bb1;
        }

        // ---- online softmax (row stats via 4-lane shuffle groups) ----
        float mx0 = -1e30f, mx1 = -1e30f;
        #pragma unroll
        for (int nf = 0; nf < 8; nf++) {
            mx0 = fmaxf(mx0, fmaxf(sc[nf][0], sc[nf][1]));
            mx1 = fmaxf(mx1, fmaxf(sc[nf][2], sc[nf][3]));
        }
        mx0 = fmaxf(mx0, __shfl_xor_sync(0xffffffffu, mx0, 1));
        mx0 = fmaxf(mx0, __shfl_xor_sync(0xffffffffu, mx0, 2));
        mx1 = fmaxf(mx1, __shfl_xor_sync(0xffffffffu, mx1, 1));
        mx1 = fmaxf(mx1, __shfl_xor_sync(0xffffffffu, mx1, 2));

        float mn0 = fmaxf(m0v, mx0), mn1 = fmaxf(m1v, mx1);
        float al0 = __expf(m0v - mn0), al1 = __expf(m1v - mn1);
        float ps0 = 0.f, ps1 = 0.f;
        #pragma unroll
        for (int nf = 0; nf < 8; nf++) {
            float p0 = __expf(sc[nf][0] - mn0);
            float p1 = __expf(sc[nf][1] - mn0);
            float p2 = __expf(sc[nf][2] - mn1);
            float p3 = __expf(sc[nf][3] - mn1);
            ps0 += p0 + p1;
            ps1 += p2 + p3;
            float2 w0, w1;
            w0.x = tf32rf(p0); w0.y = tf32rf(p1);
            w1.x = tf32rf(p2); w1.y = tf32rf(p3);
            *(float2*)&Pw[lg * KVSTR + nf * 8 + 2 * lq] = w0;
            *(float2*)&Pw[(lg + 8) * KVSTR + nf * 8 + 2 * lq] = w1;
        }
        ps0 += __shfl_xor_sync(0xffffffffu, ps0, 1);
        ps0 += __shfl_xor_sync(0xffffffffu, ps0, 2);
        ps1 += __shfl_xor_sync(0xffffffffu, ps1, 1);
        ps1 += __shfl_xor_sync(0xffffffffu, ps1, 2);
        l0 = l0 * al0 + ps0;
        l1 = l1 * al1 + ps1;
        m0v = mn0; m1v = mn1;

        #pragma unroll
        for (int nf = 0; nf < 8; nf++) {
            oc[nf][0] *= al0; oc[nf][1] *= al0;
            oc[nf][2] *= al1; oc[nf][3] *= al1;
        }
        __syncwarp();

        // ---- O += P @ V chunk ----
        #pragma unroll
        for (int kb = 0; kb < 8; kb++) {
            unsigned pa[4];
            pa[0] = __float_as_uint(Pw[lg * KVSTR + kb * 8 + lq]);
            pa[1] = __float_as_uint(Pw[(lg + 8) * KVSTR + kb * 8 + lq]);
            pa[2] = __float_as_uint(Pw[lg * KVSTR + kb * 8 + lq + 4]);
            pa[3] = __float_as_uint(Pw[(lg + 8) * KVSTR + kb * 8 + lq + 4]);
            #pragma unroll
            for (int nf = 0; nf < 8; nf++) {
                unsigned b[2];
                b[0] = __float_as_uint(Vs[(kc + kb * 8 + lq) * KVSTR + nf * 8 + lg]);
                b[1] = __float_as_uint(Vs[(kc + kb * 8 + lq + 4) * KVSTR + nf * 8 + lg]);
                mma_tf32(oc[nf], pa, b);
            }
        }
        __syncwarp();   // Pw reused next chunk
    }

    // ---- epilogue: normalize, gate, write ----
    float inv0 = 1.0f / l0, inv1 = 1.0f / l1;
    #pragma unroll
    for (int nf = 0; nf < 8; nf++) {
        int d = nf * 8 + 2 * lq;
        float bg0 = bg[h * 64 + d], bg1 = bg[h * 64 + d + 1];
        size_t a0 = base + (size_t)row0 * HD + d;
        size_t a1 = base + (size_t)(row0 + 8) * HD + d;
        float2 gv0 = *(const float2*)&g_g[a0];
        float2 gv1 = *(const float2*)&g_g[a1];
        float2 o0, o1;
        o0.x = oc[nf][0] * inv0 * (1.0f / (1.0f + __expf(-(gv0.x + bg0))));
        o0.y = oc[nf][1] * inv0 * (1.0f / (1.0f + __expf(-(gv0.y + bg1))));
        o1.x = oc[nf][2] * inv1 * (1.0f / (1.0f + __expf(-(gv1.x + bg0))));
        o1.y = oc[nf][3] * inv1 * (1.0f / (1.0f + __expf(-(gv1.y + bg1))));
        *(float2*)&g_o[a0] = o0;
        *(float2*)&g_o[a1] = o1;
    }
}

// ============================= launch ==============================
extern "C" void kernel_launch(void* const* d_in, const int* in_sizes, int n_in,
                              void* d_out, int out_size) {
    const float* x     = (const float*)d_in[0];
    const float* mask  = (const float*)d_in[1];
    const float* gamma = (const float*)d_in[2];
    const float* beta  = (const float*)d_in[3];
    const float* Wq    = (const float*)d_in[4];
    const float* Wk    = (const float*)d_in[5];
    const float* Wv    = (const float*)d_in[6];
    const float* Wg    = (const float*)d_in[7];
    const float* bg    = (const float*)d_in[8];
    const float* Wo    = (const float*)d_in[9];
    const float* bo    = (const float*)d_in[10];
    float* out = (float*)d_out;

    const int attn_smem = ATTN_SMEM_FLOATS * (int)sizeof(float);  // ~210 KB
    cudaFuncSetAttribute(attn_tc, cudaFuncAttributeMaxDynamicSharedMemorySize, attn_smem);

    // 1) LayerNorm
    ln_kernel<<<NROW, 256>>>(x, gamma, beta);

    // 2) projections: Q, K, V, G = xn @ W*  (M=65536, N=512, K=256)
    dim3 gproj(4, 512);
    gemm_tc<<<gproj, 256>>>(Wq, nullptr, nullptr, 0, CDIM, HD, HD);
    gemm_tc<<<gproj, 256>>>(Wk, nullptr, nullptr, 1, CDIM, HD, HD);
    gemm_tc<<<gproj, 256>>>(Wv, nullptr, nullptr, 2, CDIM, HD, HD);
    gemm_tc<<<gproj, 256>>>(Wg, nullptr, nullptr, 3, CDIM, HD, HD);

    // 3) attention + gate per (h, i)
    attn_tc<<<dim3(HDIM, IDIM), 512, attn_smem>>>(mask, bg);

    // 4) output projection: out = o @ Wo + bo  (M=65536, N=256, K=512)
    gemm_tc<<<dim3(2, 512), 256>>>(Wo, bo, out, 4, HD, CDIM, CDIM);
}